// round 8
// baseline (speedup 1.0000x reference)
#include <cuda_runtime.h>
#include <cuda_fp16.h>

// TrilinearInterpolation, two-phase single-launch version.
// d_out = [lut passthrough (107811 f32)][out (32,3,512,512) f32].
//
// Phase 1: smem = half2(ch0[i], ch1[i])           -> 8 LDS.32/px, 2 channels
// Phase 2: smem = u32( h(ch2[i]), h(ch2[i+1]) )   -> 4 LDS.32/px (x-pair packed)
// Same 143748-B smem buffer restaged between phases. Each CTA owns a
// contiguous pixel chunk; phase 2 walks it in reverse for L2 reuse of the
// phase-1 image reads. 1 px/thread/iter => dense (1-wavefront) LDG/STG.

constexpr int D   = 33;
constexpr int DD  = D * D;          // 1089
constexpr int D3  = D * D * D;      // 35937
constexpr int HW  = 512 * 512;      // 262144
constexpr int NPX = 32 * HW;        // 8388608 pixels
constexpr int SMEM_BYTES = D3 * 4;  // 143748

// Pre-converted LUT tables (device globals: no allocation allowed).
__device__ unsigned int g_pair01[D3];  // (h(ch0[i]), h(ch1[i]))
__device__ unsigned int g_ch2p[D3];    // (h(ch2[i]), h(ch2[i+1]))

// One-shot conversion + fp32 LUT passthrough copy.
__global__ void cvt_lut_kernel(const float* __restrict__ lut, float* __restrict__ out)
{
    int i = blockIdx.x * 256 + threadIdx.x;
    if (i < D3) {
        __half2 p01 = __floats2half2_rn(lut[i], lut[D3 + i]);
        g_pair01[i] = *reinterpret_cast<unsigned int*>(&p01);
        int ip1 = (i + 1 < D3) ? i + 1 : i;
        __half2 p2 = __floats2half2_rn(lut[2 * D3 + i], lut[2 * D3 + ip1]);
        g_ch2p[i] = *reinterpret_cast<unsigned int*>(&p2);
    }
    // LUT passthrough: 107811 floats over the whole grid.
    int nthr = gridDim.x * 256;
    for (int j = i; j < 3 * D3; j += nthr)
        out[j] = lut[j];
}

__device__ __forceinline__ void coords(float r, float g, float b,
                                       int& base, float& wx, float& wy, float& wz)
{
    const float S = 32.0f, S1 = 31.0f;
    float x = fminf(fmaxf(r * S, 0.0f), S);
    float y = fminf(fmaxf(g * S, 0.0f), S);
    float z = fminf(fmaxf(b * S, 0.0f), S);
    float x0 = fminf(floorf(x), S1);
    float y0 = fminf(floorf(y), S1);
    float z0 = fminf(floorf(z), S1);
    wx = x - x0; wy = y - y0; wz = z - z0;
    base = (int)z0 * DD + (int)y0 * D + (int)x0;
}

__global__ __launch_bounds__(1024, 1)
void trilerp_kernel(const float* __restrict__ img, float* __restrict__ out)
{
    extern __shared__ unsigned int sm[];

    // Contiguous pixel chunk for this CTA.
    const int chunk = (NPX + gridDim.x - 1) / gridDim.x;
    const int start = blockIdx.x * chunk;
    const int end   = min(start + chunk, NPX);
    const int tid   = threadIdx.x;

    // ---------------- Phase 1: channels 0 + 1 ----------------
    for (int i = tid; i < D3; i += 1024)
        sm[i] = __ldg(g_pair01 + i);
    __syncthreads();

    const __half2* sp = reinterpret_cast<const __half2*>(sm);

    for (int px = start + tid; px < end; px += 1024) {
        const int n  = px >> 18;            // px / HW
        const int hw = px & (HW - 1);
        const int ib = (n * 3) << 18;       // (n*3)*HW

        float r = __ldg(img + ib + hw);
        float g = __ldg(img + ib + HW + hw);
        float b = __ldg(img + ib + 2 * HW + hw);

        int base; float wx, wy, wz;
        coords(r, g, b, base, wx, wy, wz);

        float2 p000 = __half22float2(sp[base]);
        float2 p001 = __half22float2(sp[base + 1]);
        float2 p010 = __half22float2(sp[base + D]);
        float2 p011 = __half22float2(sp[base + D + 1]);
        float2 p100 = __half22float2(sp[base + DD]);
        float2 p101 = __half22float2(sp[base + DD + 1]);
        float2 p110 = __half22float2(sp[base + DD + D]);
        float2 p111 = __half22float2(sp[base + DD + D + 1]);

        float a00 = fmaf(wx, p001.x - p000.x, p000.x);
        float a01 = fmaf(wx, p011.x - p010.x, p010.x);
        float a10 = fmaf(wx, p101.x - p100.x, p100.x);
        float a11 = fmaf(wx, p111.x - p110.x, p110.x);
        float b0  = fmaf(wy, a01 - a00, a00);
        float b1  = fmaf(wy, a11 - a10, a10);
        float r0  = fmaf(wz, b1 - b0, b0);

        a00 = fmaf(wx, p001.y - p000.y, p000.y);
        a01 = fmaf(wx, p011.y - p010.y, p010.y);
        a10 = fmaf(wx, p101.y - p100.y, p100.y);
        a11 = fmaf(wx, p111.y - p110.y, p110.y);
        b0  = fmaf(wy, a01 - a00, a00);
        b1  = fmaf(wy, a11 - a10, a10);
        float r1 = fmaf(wz, b1 - b0, b0);

        out[ib + hw]      = r0;   // c=0 plane (same index math as img r-plane)
        out[ib + HW + hw] = r1;   // c=1 plane
    }

    // ---------------- Phase 2: channel 2 (x-pair packed) ----------------
    __syncthreads();
    for (int i = tid; i < D3; i += 1024)
        sm[i] = __ldg(g_ch2p + i);
    __syncthreads();

    const __half2* s2 = reinterpret_cast<const __half2*>(sm);

    // Reverse walk: start from the pixels phase 1 touched most recently (L2-warm).
    for (int px = end - 1 - tid; px >= start; px -= 1024) {
        const int n  = px >> 18;
        const int hw = px & (HW - 1);
        const int ib = (n * 3) << 18;

        float r = __ldg(img + ib + hw);
        float g = __ldg(img + ib + HW + hw);
        float b = __ldg(img + ib + 2 * HW + hw);

        int base; float wx, wy, wz;
        coords(r, g, b, base, wx, wy, wz);

        // Each half2 holds (v[i], v[i+1]): both x-corners in one LDS.32.
        float2 e00 = __half22float2(s2[base]);
        float2 e01 = __half22float2(s2[base + D]);
        float2 e10 = __half22float2(s2[base + DD]);
        float2 e11 = __half22float2(s2[base + DD + D]);

        float a00 = fmaf(wx, e00.y - e00.x, e00.x);
        float a01 = fmaf(wx, e01.y - e01.x, e01.x);
        float a10 = fmaf(wx, e10.y - e10.x, e10.x);
        float a11 = fmaf(wx, e11.y - e11.x, e11.x);
        float b0  = fmaf(wy, a01 - a00, a00);
        float b1  = fmaf(wy, a11 - a10, a10);

        out[ib + 2 * HW + hw] = fmaf(wz, b1 - b0, b0);  // c=2 plane
    }
}

extern "C" void kernel_launch(void* const* d_in, const int* in_sizes, int n_in,
                              void* d_out, int out_size)
{
    const float* lut = (const float*)d_in[0];
    const float* img = (const float*)d_in[1];
    if (n_in >= 2 && in_sizes[0] > in_sizes[1]) {   // defensive input-order check
        lut = (const float*)d_in[1];
        img = (const float*)d_in[0];
    }
    float* out = (float*)d_out;

    // Convert LUT to fp16 tables + copy fp32 LUT into tuple slot 0.
    cvt_lut_kernel<<<(D3 + 255) / 256, 256>>>(lut, out);

    cudaFuncSetAttribute(trilerp_kernel,
                         cudaFuncAttributeMaxDynamicSharedMemorySize, SMEM_BYTES);

    int sms = 148;
    cudaDeviceGetAttribute(&sms, cudaDevAttrMultiProcessorCount, 0);

    trilerp_kernel<<<sms, 1024, SMEM_BYTES>>>(img, out + 3 * D3);
}

// round 9
// speedup vs baseline: 1.2783x; 1.2783x over previous
#include <cuda_runtime.h>
#include <cuda_fp16.h>

// TrilinearInterpolation, two-phase + 4-px/thread ILP version.
// d_out = [lut passthrough (107811 f32)][out (32,3,512,512) f32].
//
// Phase 1: smem = half2(ch0[i], ch1[i])          -> 8 LDS.32/px (2 channels)
// Phase 2: smem = half2(ch2[i], ch2[i+1])        -> 4 LDS.32/px (x-pair packed)
// 143748-B smem buffer restaged between phases. Each CTA owns a contiguous
// pixel chunk; all global access is lane-consecutive (dense 128B wavefronts).
// 4 pixels/thread with all 12 LDGs issued up front to hide memory latency
// (R8 was scoreboard-bound at MLP=3).

constexpr int D   = 33;
constexpr int DD  = D * D;          // 1089
constexpr int D3  = D * D * D;      // 35937
constexpr int HW  = 512 * 512;      // 262144
constexpr int NPX = 32 * HW;        // 8388608 pixels
constexpr int SMEM_BYTES = D3 * 4;  // 143748
constexpr int BLK = 1024;
constexpr int UNROLL = 4;
constexpr int STEP = BLK * UNROLL;  // 4096 px per CTA iteration

// Pre-converted LUT tables (device globals: no allocation allowed).
__device__ unsigned int g_pair01[D3];  // (h(ch0[i]), h(ch1[i]))
__device__ unsigned int g_ch2p[D3];    // (h(ch2[i]), h(ch2[i+1]))

__global__ void cvt_lut_kernel(const float* __restrict__ lut, float* __restrict__ out)
{
    int i = blockIdx.x * 256 + threadIdx.x;
    if (i < D3) {
        __half2 p01 = __floats2half2_rn(lut[i], lut[D3 + i]);
        g_pair01[i] = *reinterpret_cast<unsigned int*>(&p01);
        int ip1 = (i + 1 < D3) ? i + 1 : i;
        __half2 p2 = __floats2half2_rn(lut[2 * D3 + i], lut[2 * D3 + ip1]);
        g_ch2p[i] = *reinterpret_cast<unsigned int*>(&p2);
    }
    int nthr = gridDim.x * 256;
    for (int j = i; j < 3 * D3; j += nthr)   // fp32 LUT passthrough
        out[j] = lut[j];
}

__device__ __forceinline__ void coords(float r, float g, float b,
                                       int& base, float& wx, float& wy, float& wz)
{
    const float S = 32.0f, S1 = 31.0f;
    float x = fminf(fmaxf(r * S, 0.0f), S);
    float y = fminf(fmaxf(g * S, 0.0f), S);
    float z = fminf(fmaxf(b * S, 0.0f), S);
    float x0 = fminf(floorf(x), S1);
    float y0 = fminf(floorf(y), S1);
    float z0 = fminf(floorf(z), S1);
    wx = x - x0; wy = y - y0; wz = z - z0;
    base = (int)z0 * DD + (int)y0 * D + (int)x0;
}

__device__ __forceinline__ void lerp01(const __half2* sp, int base,
                                       float wx, float wy, float wz,
                                       float& r0, float& r1)
{
    float2 p000 = __half22float2(sp[base]);
    float2 p001 = __half22float2(sp[base + 1]);
    float2 p010 = __half22float2(sp[base + D]);
    float2 p011 = __half22float2(sp[base + D + 1]);
    float2 p100 = __half22float2(sp[base + DD]);
    float2 p101 = __half22float2(sp[base + DD + 1]);
    float2 p110 = __half22float2(sp[base + DD + D]);
    float2 p111 = __half22float2(sp[base + DD + D + 1]);

    float a00 = fmaf(wx, p001.x - p000.x, p000.x);
    float a01 = fmaf(wx, p011.x - p010.x, p010.x);
    float a10 = fmaf(wx, p101.x - p100.x, p100.x);
    float a11 = fmaf(wx, p111.x - p110.x, p110.x);
    float b0  = fmaf(wy, a01 - a00, a00);
    float b1  = fmaf(wy, a11 - a10, a10);
    r0 = fmaf(wz, b1 - b0, b0);

    a00 = fmaf(wx, p001.y - p000.y, p000.y);
    a01 = fmaf(wx, p011.y - p010.y, p010.y);
    a10 = fmaf(wx, p101.y - p100.y, p100.y);
    a11 = fmaf(wx, p111.y - p110.y, p110.y);
    b0  = fmaf(wy, a01 - a00, a00);
    b1  = fmaf(wy, a11 - a10, a10);
    r1 = fmaf(wz, b1 - b0, b0);
}

__device__ __forceinline__ float lerp2(const __half2* s2, int base,
                                       float wx, float wy, float wz)
{
    float2 e00 = __half22float2(s2[base]);
    float2 e01 = __half22float2(s2[base + D]);
    float2 e10 = __half22float2(s2[base + DD]);
    float2 e11 = __half22float2(s2[base + DD + D]);

    float a00 = fmaf(wx, e00.y - e00.x, e00.x);
    float a01 = fmaf(wx, e01.y - e01.x, e01.x);
    float a10 = fmaf(wx, e10.y - e10.x, e10.x);
    float a11 = fmaf(wx, e11.y - e11.x, e11.x);
    float b0  = fmaf(wy, a01 - a00, a00);
    float b1  = fmaf(wy, a11 - a10, a10);
    return fmaf(wz, b1 - b0, b0);
}

__global__ __launch_bounds__(BLK, 1)
void trilerp_kernel(const float* __restrict__ img, float* __restrict__ out)
{
    extern __shared__ unsigned int sm[];

    const int chunk = (NPX + gridDim.x - 1) / gridDim.x;
    const int start = blockIdx.x * chunk;
    const int end   = min(start + chunk, NPX);
    const int tid   = threadIdx.x;
    const int nfull = (end - start) / STEP;            // full 4096-px blocks
    const int tail  = start + nfull * STEP;

    // ---------------- Phase 1: channels 0 + 1 ----------------
    for (int i = tid; i < D3; i += BLK)
        sm[i] = __ldg(g_pair01 + i);
    __syncthreads();
    const __half2* sp = reinterpret_cast<const __half2*>(sm);

    for (int blk = 0; blk < nfull; ++blk) {
        const int p0 = start + blk * STEP + tid;
        float r[UNROLL], g[UNROLL], b[UNROLL];
        // Batched loads: 12 outstanding LDGs, all dense 128B wavefronts.
        #pragma unroll
        for (int k = 0; k < UNROLL; ++k) {
            int px = p0 + k * BLK;
            int n  = px >> 18;
            int hw = px & (HW - 1);
            int ib = (n * 3) << 18;
            r[k] = __ldg(img + ib + hw);
            g[k] = __ldg(img + ib + HW + hw);
            b[k] = __ldg(img + ib + 2 * HW + hw);
        }
        #pragma unroll
        for (int k = 0; k < UNROLL; ++k) {
            int px = p0 + k * BLK;
            int n  = px >> 18;
            int hw = px & (HW - 1);
            int ib = (n * 3) << 18;
            int base; float wx, wy, wz;
            coords(r[k], g[k], b[k], base, wx, wy, wz);
            float r0, r1;
            lerp01(sp, base, wx, wy, wz, r0, r1);
            out[ib + hw]      = r0;
            out[ib + HW + hw] = r1;
        }
    }
    for (int px = tail + tid; px < end; px += BLK) {   // remainder
        int n  = px >> 18;
        int hw = px & (HW - 1);
        int ib = (n * 3) << 18;
        float r = __ldg(img + ib + hw);
        float g = __ldg(img + ib + HW + hw);
        float b = __ldg(img + ib + 2 * HW + hw);
        int base; float wx, wy, wz;
        coords(r, g, b, base, wx, wy, wz);
        float r0, r1;
        lerp01(sp, base, wx, wy, wz, r0, r1);
        out[ib + hw]      = r0;
        out[ib + HW + hw] = r1;
    }

    // ---------------- Phase 2: channel 2 (x-pair packed) ----------------
    __syncthreads();
    for (int i = tid; i < D3; i += BLK)
        sm[i] = __ldg(g_ch2p + i);
    __syncthreads();
    const __half2* s2 = reinterpret_cast<const __half2*>(sm);

    for (int px = tail + tid; px < end; px += BLK) {   // remainder first (L2-warm)
        int n  = px >> 18;
        int hw = px & (HW - 1);
        int ib = (n * 3) << 18;
        float r = __ldg(img + ib + hw);
        float g = __ldg(img + ib + HW + hw);
        float b = __ldg(img + ib + 2 * HW + hw);
        int base; float wx, wy, wz;
        coords(r, g, b, base, wx, wy, wz);
        out[ib + 2 * HW + hw] = lerp2(s2, base, wx, wy, wz);
    }
    // Walk blocks in reverse: most recently touched pixels first.
    for (int blk = nfull - 1; blk >= 0; --blk) {
        const int p0 = start + blk * STEP + tid;
        float r[UNROLL], g[UNROLL], b[UNROLL];
        #pragma unroll
        for (int k = 0; k < UNROLL; ++k) {
            int px = p0 + k * BLK;
            int n  = px >> 18;
            int hw = px & (HW - 1);
            int ib = (n * 3) << 18;
            r[k] = __ldg(img + ib + hw);
            g[k] = __ldg(img + ib + HW + hw);
            b[k] = __ldg(img + ib + 2 * HW + hw);
        }
        #pragma unroll
        for (int k = 0; k < UNROLL; ++k) {
            int px = p0 + k * BLK;
            int n  = px >> 18;
            int hw = px & (HW - 1);
            int ib = (n * 3) << 18;
            int base; float wx, wy, wz;
            coords(r[k], g[k], b[k], base, wx, wy, wz);
            out[ib + 2 * HW + hw] = lerp2(s2, base, wx, wy, wz);
        }
    }
}

extern "C" void kernel_launch(void* const* d_in, const int* in_sizes, int n_in,
                              void* d_out, int out_size)
{
    const float* lut = (const float*)d_in[0];
    const float* img = (const float*)d_in[1];
    if (n_in >= 2 && in_sizes[0] > in_sizes[1]) {   // defensive input-order check
        lut = (const float*)d_in[1];
        img = (const float*)d_in[0];
    }
    float* out = (float*)d_out;

    cvt_lut_kernel<<<(D3 + 255) / 256, 256>>>(lut, out);

    cudaFuncSetAttribute(trilerp_kernel,
                         cudaFuncAttributeMaxDynamicSharedMemorySize, SMEM_BYTES);

    int sms = 148;
    cudaDeviceGetAttribute(&sms, cudaDevAttrMultiProcessorCount, 0);

    trilerp_kernel<<<sms, BLK, SMEM_BYTES>>>(img, out + 3 * D3);
}

// round 10
// speedup vs baseline: 1.3999x; 1.0951x over previous
#include <cuda_runtime.h>
#include <cuda_fp16.h>

// TrilinearInterpolation, CTA-specialized version (no temporal phases).
// d_out = [lut passthrough (107811 f32)][out (32,3,512,512) f32].
//
// CTAs 0..n1-1   : smem = half2(ch0[i], ch1[i])        -> 8 LDS.32/px, ch0+ch1
// CTAs n1..grid-1: smem = half2(c2[i], c2[i+1]-c2[i])  -> 4 LDS.32/px, ch2
// n1 = 2/3 of grid balances the smem-crossbar cycles (8:4 LDS ratio).
// Work = 2048 blocks of 4096 px; each block lies in one image plane, so the
// plane base is computed once per block. Grid-stride over blocks per group.

constexpr int D   = 33;
constexpr int DD  = D * D;          // 1089
constexpr int D3  = D * D * D;      // 35937
constexpr int HW  = 512 * 512;      // 262144
constexpr int NPX = 32 * HW;        // 8388608
constexpr int SMEM_BYTES = D3 * 4;  // 143748
constexpr int BLK = 1024;
constexpr int UNROLL = 4;
constexpr int STEP = BLK * UNROLL;      // 4096 (divides HW)
constexpr int NBLOCKS = NPX / STEP;     // 2048, exact

// Pre-converted LUT tables (device globals: no allocation allowed).
__device__ unsigned int g_pair01[D3];  // (h(ch0[i]), h(ch1[i]))
__device__ unsigned int g_ch2d[D3];    // (h(ch2[i]), h(ch2[i+1]-ch2[i]))

__global__ void cvt_lut_kernel(const float* __restrict__ lut, float* __restrict__ out)
{
    int i = blockIdx.x * 256 + threadIdx.x;
    if (i < D3) {
        __half2 p01 = __floats2half2_rn(lut[i], lut[D3 + i]);
        g_pair01[i] = *reinterpret_cast<unsigned int*>(&p01);
        float v = lut[2 * D3 + i];
        float d = (i + 1 < D3) ? lut[2 * D3 + i + 1] - v : 0.0f;
        __half2 vd = __floats2half2_rn(v, d);
        g_ch2d[i] = *reinterpret_cast<unsigned int*>(&vd);
    }
    int nthr = gridDim.x * 256;
    for (int j = i; j < 3 * D3; j += nthr)   // fp32 LUT passthrough
        out[j] = lut[j];
}

__device__ __forceinline__ void coords(float r, float g, float b,
                                       int& base, float& wx, float& wy, float& wz)
{
    const float S = 32.0f, S1 = 31.0f;
    float x = fminf(fmaxf(r * S, 0.0f), S);
    float y = fminf(fmaxf(g * S, 0.0f), S);
    float z = fminf(fmaxf(b * S, 0.0f), S);
    float x0 = fminf(floorf(x), S1);
    float y0 = fminf(floorf(y), S1);
    float z0 = fminf(floorf(z), S1);
    wx = x - x0; wy = y - y0; wz = z - z0;
    base = (int)z0 * DD + (int)y0 * D + (int)x0;
}

__global__ __launch_bounds__(BLK, 1)
void trilerp_kernel(const float* __restrict__ img, float* __restrict__ out)
{
    extern __shared__ unsigned int sm[];
    const int tid = threadIdx.x;
    const int n1  = (2 * gridDim.x) / 3;          // ch0+ch1 CTAs
    const bool is01 = (int)blockIdx.x < n1;

    // Stage this group's table (L2-resident after first CTAs).
    {
        const unsigned int* src = is01 ? g_pair01 : g_ch2d;
        for (int i = tid; i < D3; i += BLK)
            sm[i] = __ldg(src + i);
    }
    __syncthreads();
    const __half2* st = reinterpret_cast<const __half2*>(sm);

    if (is01) {
        // ---- channels 0 + 1: 8 half2 gathers per pixel ----
        for (int blk = blockIdx.x; blk < NBLOCKS; blk += n1) {
            const int px0 = blk * STEP;
            const int n   = px0 >> 18;                 // image index (const per block)
            const int ib  = (n * 3) << 18;             // plane base
            const int hw0 = (px0 & (HW - 1)) + tid;

            float r[UNROLL], g[UNROLL], b[UNROLL];
            #pragma unroll
            for (int k = 0; k < UNROLL; ++k) {         // 12 dense LDGs up front
                int hw = hw0 + k * BLK;
                r[k] = __ldg(img + ib + hw);
                g[k] = __ldg(img + ib + HW + hw);
                b[k] = __ldg(img + ib + 2 * HW + hw);
            }
            #pragma unroll
            for (int k = 0; k < UNROLL; ++k) {
                int base; float wx, wy, wz;
                coords(r[k], g[k], b[k], base, wx, wy, wz);

                float2 p000 = __half22float2(st[base]);
                float2 p001 = __half22float2(st[base + 1]);
                float2 p010 = __half22float2(st[base + D]);
                float2 p011 = __half22float2(st[base + D + 1]);
                float2 p100 = __half22float2(st[base + DD]);
                float2 p101 = __half22float2(st[base + DD + 1]);
                float2 p110 = __half22float2(st[base + DD + D]);
                float2 p111 = __half22float2(st[base + DD + D + 1]);

                float a00 = fmaf(wx, p001.x - p000.x, p000.x);
                float a01 = fmaf(wx, p011.x - p010.x, p010.x);
                float a10 = fmaf(wx, p101.x - p100.x, p100.x);
                float a11 = fmaf(wx, p111.x - p110.x, p110.x);
                float b0  = fmaf(wy, a01 - a00, a00);
                float b1  = fmaf(wy, a11 - a10, a10);
                float r0  = fmaf(wz, b1 - b0, b0);

                a00 = fmaf(wx, p001.y - p000.y, p000.y);
                a01 = fmaf(wx, p011.y - p010.y, p010.y);
                a10 = fmaf(wx, p101.y - p100.y, p100.y);
                a11 = fmaf(wx, p111.y - p110.y, p110.y);
                b0  = fmaf(wy, a01 - a00, a00);
                b1  = fmaf(wy, a11 - a10, a10);
                float r1 = fmaf(wz, b1 - b0, b0);

                int hw = hw0 + k * BLK;
                __stcs(out + ib + hw, r0);             // c=0 plane
                __stcs(out + ib + HW + hw, r1);        // c=1 plane
            }
        }
    } else {
        // ---- channel 2: 4 (value,delta) gathers per pixel ----
        for (int blk = blockIdx.x - n1; blk < NBLOCKS; blk += (int)gridDim.x - n1) {
            const int px0 = blk * STEP;
            const int n   = px0 >> 18;
            const int ib  = (n * 3) << 18;
            const int hw0 = (px0 & (HW - 1)) + tid;

            float r[UNROLL], g[UNROLL], b[UNROLL];
            #pragma unroll
            for (int k = 0; k < UNROLL; ++k) {
                int hw = hw0 + k * BLK;
                r[k] = __ldg(img + ib + hw);
                g[k] = __ldg(img + ib + HW + hw);
                b[k] = __ldg(img + ib + 2 * HW + hw);
            }
            #pragma unroll
            for (int k = 0; k < UNROLL; ++k) {
                int base; float wx, wy, wz;
                coords(r[k], g[k], b[k], base, wx, wy, wz);

                float2 e00 = __half22float2(st[base]);          // (v, v_next - v)
                float2 e01 = __half22float2(st[base + D]);
                float2 e10 = __half22float2(st[base + DD]);
                float2 e11 = __half22float2(st[base + DD + D]);

                float a00 = fmaf(wx, e00.y, e00.x);
                float a01 = fmaf(wx, e01.y, e01.x);
                float a10 = fmaf(wx, e10.y, e10.x);
                float a11 = fmaf(wx, e11.y, e11.x);
                float b0  = fmaf(wy, a01 - a00, a00);
                float b1  = fmaf(wy, a11 - a10, a10);

                int hw = hw0 + k * BLK;
                __stcs(out + ib + 2 * HW + hw, fmaf(wz, b1 - b0, b0));  // c=2
            }
        }
    }
}

extern "C" void kernel_launch(void* const* d_in, const int* in_sizes, int n_in,
                              void* d_out, int out_size)
{
    const float* lut = (const float*)d_in[0];
    const float* img = (const float*)d_in[1];
    if (n_in >= 2 && in_sizes[0] > in_sizes[1]) {   // defensive input-order check
        lut = (const float*)d_in[1];
        img = (const float*)d_in[0];
    }
    float* out = (float*)d_out;

    cvt_lut_kernel<<<(D3 + 255) / 256, 256>>>(lut, out);

    cudaFuncSetAttribute(trilerp_kernel,
                         cudaFuncAttributeMaxDynamicSharedMemorySize, SMEM_BYTES);

    int sms = 148;
    cudaDeviceGetAttribute(&sms, cudaDevAttrMultiProcessorCount, 0);

    trilerp_kernel<<<sms, BLK, SMEM_BYTES>>>(img, out + 3 * D3);
}

// round 11
// speedup vs baseline: 1.4603x; 1.0431x over previous
#include <cuda_runtime.h>
#include <cuda_fp16.h>

// TrilinearInterpolation, CTA-specialized, latency-tuned per group.
// d_out = [lut passthrough (107811 f32)][out (32,3,512,512) f32].
//
// CTAs [0, n1)      : smem = half2(ch0[i], ch1[i])       8 LDS/px, ch0+ch1, UNROLL=4
// CTAs [n1, grid)   : smem = half2(c2[i], c2[i+1]-c2[i]) 4 LDS/px, ch2,     UNROLL=8
// n1/n2 = 128.8/70.4 (L1-wavefront balance incl. LDG/STG) -> n1 = grid*129/200.
// ch2 runs 8 px/thread (24 LDGs in flight) because at 4 px/thread its L1
// demand (70.4 cyc/iter x 8 warps) is below the ~750-cyc latency window.

constexpr int D   = 33;
constexpr int DD  = D * D;          // 1089
constexpr int D3  = D * D * D;      // 35937
constexpr int HW  = 512 * 512;      // 262144
constexpr int NPX = 32 * HW;        // 8388608
constexpr int SMEM_BYTES = D3 * 4;  // 143748
constexpr int BLK = 1024;

constexpr int U1 = 4;
constexpr int STEP1 = BLK * U1;         // 4096 (divides HW)
constexpr int NB1   = NPX / STEP1;      // 2048

constexpr int U2 = 8;
constexpr int STEP2 = BLK * U2;         // 8192 (divides HW)
constexpr int NB2   = NPX / STEP2;      // 1024

// Pre-converted LUT tables (device globals: no allocation allowed).
__device__ unsigned int g_pair01[D3];  // (h(ch0[i]), h(ch1[i]))
__device__ unsigned int g_ch2d[D3];    // (h(ch2[i]), h(ch2[i+1]-ch2[i]))

__global__ void cvt_lut_kernel(const float* __restrict__ lut, float* __restrict__ out)
{
    int i = blockIdx.x * 256 + threadIdx.x;
    if (i < D3) {
        __half2 p01 = __floats2half2_rn(lut[i], lut[D3 + i]);
        g_pair01[i] = *reinterpret_cast<unsigned int*>(&p01);
        float v = lut[2 * D3 + i];
        float d = (i + 1 < D3) ? lut[2 * D3 + i + 1] - v : 0.0f;
        __half2 vd = __floats2half2_rn(v, d);
        g_ch2d[i] = *reinterpret_cast<unsigned int*>(&vd);
    }
    int nthr = gridDim.x * 256;
    for (int j = i; j < 3 * D3; j += nthr)   // fp32 LUT passthrough
        out[j] = lut[j];
}

__device__ __forceinline__ void coords(float r, float g, float b,
                                       int& base, float& wx, float& wy, float& wz)
{
    const float S = 32.0f, S1 = 31.0f;
    float x = fminf(fmaxf(r * S, 0.0f), S);
    float y = fminf(fmaxf(g * S, 0.0f), S);
    float z = fminf(fmaxf(b * S, 0.0f), S);
    float x0 = fminf(floorf(x), S1);
    float y0 = fminf(floorf(y), S1);
    float z0 = fminf(floorf(z), S1);
    wx = x - x0; wy = y - y0; wz = z - z0;
    base = (int)z0 * DD + (int)y0 * D + (int)x0;
}

__global__ __launch_bounds__(BLK, 1)
void trilerp_kernel(const float* __restrict__ img, float* __restrict__ out)
{
    extern __shared__ unsigned int sm[];
    const int tid = threadIdx.x;
    const int n1  = ((int)gridDim.x * 129) / 200;   // 98 of 152
    const bool is01 = (int)blockIdx.x < n1;

    // Stage this group's table (L2-resident after the first CTAs).
    {
        const unsigned int* src = is01 ? g_pair01 : g_ch2d;
        #pragma unroll 4
        for (int i = tid; i < D3; i += BLK)
            sm[i] = __ldg(src + i);
    }
    __syncthreads();
    const __half2* st = reinterpret_cast<const __half2*>(sm);

    if (is01) {
        // ---- channels 0 + 1: 8 half2 gathers per pixel, 4 px/thread ----
        for (int blk = blockIdx.x; blk < NB1; blk += n1) {
            const int px0 = blk * STEP1;
            const int n   = px0 >> 18;                 // image index (const per block)
            const int ib  = (n * 3) << 18;             // plane base
            const int hw0 = (px0 & (HW - 1)) + tid;

            float r[U1], g[U1], b[U1];
            #pragma unroll
            for (int k = 0; k < U1; ++k) {             // 12 dense LDGs up front
                int hw = hw0 + k * BLK;
                r[k] = __ldg(img + ib + hw);
                g[k] = __ldg(img + ib + HW + hw);
                b[k] = __ldg(img + ib + 2 * HW + hw);
            }
            #pragma unroll
            for (int k = 0; k < U1; ++k) {
                int base; float wx, wy, wz;
                coords(r[k], g[k], b[k], base, wx, wy, wz);

                float2 p000 = __half22float2(st[base]);
                float2 p001 = __half22float2(st[base + 1]);
                float2 p010 = __half22float2(st[base + D]);
                float2 p011 = __half22float2(st[base + D + 1]);
                float2 p100 = __half22float2(st[base + DD]);
                float2 p101 = __half22float2(st[base + DD + 1]);
                float2 p110 = __half22float2(st[base + DD + D]);
                float2 p111 = __half22float2(st[base + DD + D + 1]);

                float a00 = fmaf(wx, p001.x - p000.x, p000.x);
                float a01 = fmaf(wx, p011.x - p010.x, p010.x);
                float a10 = fmaf(wx, p101.x - p100.x, p100.x);
                float a11 = fmaf(wx, p111.x - p110.x, p110.x);
                float b0  = fmaf(wy, a01 - a00, a00);
                float b1  = fmaf(wy, a11 - a10, a10);
                float r0  = fmaf(wz, b1 - b0, b0);

                a00 = fmaf(wx, p001.y - p000.y, p000.y);
                a01 = fmaf(wx, p011.y - p010.y, p010.y);
                a10 = fmaf(wx, p101.y - p100.y, p100.y);
                a11 = fmaf(wx, p111.y - p110.y, p110.y);
                b0  = fmaf(wy, a01 - a00, a00);
                b1  = fmaf(wy, a11 - a10, a10);
                float r1 = fmaf(wz, b1 - b0, b0);

                int hw = hw0 + k * BLK;
                __stcs(out + ib + hw, r0);             // c=0 plane
                __stcs(out + ib + HW + hw, r1);        // c=1 plane
            }
        }
    } else {
        // ---- channel 2: 4 (value,delta) gathers per pixel, 8 px/thread ----
        const int n2 = (int)gridDim.x - n1;
        for (int blk = blockIdx.x - n1; blk < NB2; blk += n2) {
            const int px0 = blk * STEP2;
            const int n   = px0 >> 18;
            const int ib  = (n * 3) << 18;
            const int hw0 = (px0 & (HW - 1)) + tid;

            float r[U2], g[U2], b[U2];
            #pragma unroll
            for (int k = 0; k < U2; ++k) {             // 24 dense LDGs up front
                int hw = hw0 + k * BLK;
                r[k] = __ldg(img + ib + hw);
                g[k] = __ldg(img + ib + HW + hw);
                b[k] = __ldg(img + ib + 2 * HW + hw);
            }
            #pragma unroll
            for (int k = 0; k < U2; ++k) {
                int base; float wx, wy, wz;
                coords(r[k], g[k], b[k], base, wx, wy, wz);

                float2 e00 = __half22float2(st[base]);          // (v, v_next - v)
                float2 e01 = __half22float2(st[base + D]);
                float2 e10 = __half22float2(st[base + DD]);
                float2 e11 = __half22float2(st[base + DD + D]);

                float a00 = fmaf(wx, e00.y, e00.x);
                float a01 = fmaf(wx, e01.y, e01.x);
                float a10 = fmaf(wx, e10.y, e10.x);
                float a11 = fmaf(wx, e11.y, e11.x);
                float b0  = fmaf(wy, a01 - a00, a00);
                float b1  = fmaf(wy, a11 - a10, a10);

                int hw = hw0 + k * BLK;
                __stcs(out + ib + 2 * HW + hw, fmaf(wz, b1 - b0, b0));  // c=2
            }
        }
    }
}

extern "C" void kernel_launch(void* const* d_in, const int* in_sizes, int n_in,
                              void* d_out, int out_size)
{
    const float* lut = (const float*)d_in[0];
    const float* img = (const float*)d_in[1];
    if (n_in >= 2 && in_sizes[0] > in_sizes[1]) {   // defensive input-order check
        lut = (const float*)d_in[1];
        img = (const float*)d_in[0];
    }
    float* out = (float*)d_out;

    cvt_lut_kernel<<<(D3 + 255) / 256, 256>>>(lut, out);

    cudaFuncSetAttribute(trilerp_kernel,
                         cudaFuncAttributeMaxDynamicSharedMemorySize, SMEM_BYTES);

    int sms = 148;
    cudaDeviceGetAttribute(&sms, cudaDevAttrMultiProcessorCount, 0);

    trilerp_kernel<<<sms, BLK, SMEM_BYTES>>>(img, out + 3 * D3);
}